// round 6
// baseline (speedup 1.0000x reference)
#include <cuda_runtime.h>
#include <cuda_bf16.h>
#include <stdint.h>
#include <math.h>

#define D    4096
#define RK   1024
#define NTOT (1u << 24)     // 4^12 probability entries

// ---------------------------------------------------------------------------
// Scratch (__device__ globals per allocation rules).
// ---------------------------------------------------------------------------
__device__ float gA_re[NTOT];
__device__ float gA_im[NTOT];
__device__ float gB_re[NTOT];
__device__ float gB_im[NTOT];
__device__ __nv_bfloat16 gHr[(size_t)D * RK];   // hi(Ur)
__device__ __nv_bfloat16 gLr[(size_t)D * RK];   // lo(Ur)
__device__ __nv_bfloat16 gHi[(size_t)D * RK];   // hi(Ui)
__device__ __nv_bfloat16 gLi[(size_t)D * RK];   // lo(Ui)
__device__ __nv_bfloat16 gHs[(size_t)D * RK];   // hi(Ur+Ui)
__device__ __nv_bfloat16 gLs[(size_t)D * RK];   // lo(Ur+Ui)
__device__ __nv_bfloat16 gHd[(size_t)D * RK];   // hi(Ur-Ui)
__device__ __nv_bfloat16 gLd[(size_t)D * RK];   // lo(Ur-Ui)
__device__ float g_inv_trace;

// ---------------------------------------------------------------------------
static __device__ __forceinline__ void mma16(float c[4], const uint32_t a[4],
                                             uint32_t b0, uint32_t b1) {
    asm volatile(
        "mma.sync.aligned.m16n8k16.row.col.f32.bf16.bf16.f32 "
        "{%0,%1,%2,%3}, {%4,%5,%6,%7}, {%8,%9}, {%0,%1,%2,%3};\n"
        : "+f"(c[0]), "+f"(c[1]), "+f"(c[2]), "+f"(c[3])
        : "r"(a[0]), "r"(a[1]), "r"(a[2]), "r"(a[3]), "r"(b0), "r"(b1));
}
static __device__ __forceinline__ void ldsm4(uint32_t r[4], uint32_t addr) {
    asm volatile("ldmatrix.sync.aligned.m8n8.x4.shared.b16 {%0,%1,%2,%3}, [%4];"
                 : "=r"(r[0]), "=r"(r[1]), "=r"(r[2]), "=r"(r[3]) : "r"(addr));
}
static __device__ __forceinline__ void cpa16(uint32_t dst, const void* src) {
    asm volatile("cp.async.cg.shared.global [%0], [%1], 16;"
                 :: "r"(dst), "l"(src));
}

// ---------------------------------------------------------------------------
// Pack: for x in {Ur, Ui, Ur+Ui, Ur-Ui}: hi = bf16(x), lo = bf16(x - hi).
// ---------------------------------------------------------------------------
__global__ void __launch_bounds__(256) pack_split(const float* __restrict__ Ur,
                                                  const float* __restrict__ Ui)
{
    unsigned e = blockIdx.x * 256u + threadIdx.x;   // 0 .. 4M-1
    float ar = Ur[e], ai = Ui[e];
    float s = ar + ai, d = ar - ai;
    __nv_bfloat16 h;
    h = __float2bfloat16_rn(ar); gHr[e] = h; gLr[e] = __float2bfloat16_rn(ar - __bfloat162float(h));
    h = __float2bfloat16_rn(ai); gHi[e] = h; gLi[e] = __float2bfloat16_rn(ai - __bfloat162float(h));
    h = __float2bfloat16_rn(s);  gHs[e] = h; gLs[e] = __float2bfloat16_rn(s  - __bfloat162float(h));
    h = __float2bfloat16_rn(d);  gHd[e] = h; gLd[e] = __float2bfloat16_rn(d  - __bfloat162float(h));
}

// ---------------------------------------------------------------------------
// rho = U U^H via Gauss 3-mult complex GEMM, bf16x3 split, mma.sync m16n8k16.
//   k1 = (a+b)c^T, k2 = a(c+d)^T, k3 = b(c-d)^T ; re = k1-k3, im = k1-k2.
// CTA tile 128x64, 256 threads, 8 warps (wm 0..1 x wn 0..3), warp tile 64x16.
// Grid: block-lower-triangle cj <= 2*bi+1 (1056 CTAs). Mirror-write only when
// the target lies in a different 128-block (diag blocks computed directly).
// 4-stage cp.async pipeline; K-chunk 16. ldmatrix.x4 fragment loads, pitch 48B.
// ---------------------------------------------------------------------------
#define APL  6144           // A plane bytes (128 rows * 48)
#define BPL  3072           // B plane bytes (64 rows * 48)
#define STG  55296          // stage bytes: 6*APL + 6*BPL
#define BOFF 36864          // 6*APL

__global__ void __launch_bounds__(256, 1) gemm_mma()
{
    extern __shared__ char sm[];
    const uint32_t smb = (uint32_t)__cvta_generic_to_shared(sm);

    const int tid  = threadIdx.x;
    const int lane = tid & 31;
    const int wid  = tid >> 5;
    const int gid  = lane >> 2;     // 0..7
    const int tig  = lane & 3;      // 0..3
    const int wm   = wid >> 2;      // 0..1
    const int wn   = wid & 3;       // 0..3
    const int lrow = lane & 15;
    const int lhalf = lane >> 4;

    // tile index: cum(bi) = bi*(bi+1); cj in [0, 2*bi+2)
    int l = blockIdx.x;
    int bi = (int)((sqrtf(4.0f * (float)l + 1.0f) - 1.0f) * 0.5f);
    while ((bi + 1) * (bi + 2) <= l) bi++;
    while (bi * (bi + 1) > l) bi--;
    int cj = l - bi * (bi + 1);
    const int row0 = bi * 128, col0 = cj * 64;
    const bool mir = (cj >> 1) != bi;

    // ---- loader: one K-chunk (16 k) into stage stg; 9 cp.async per thread ----
    auto load_chunk = [&](int stg, int k0) {
        uint32_t base = smb + stg * STG;
        int r = tid >> 1, half = tid & 1;
        size_t asrc = (size_t)(row0 + r) * RK + k0 + half * 8;
        uint32_t adst = base + r * 48 + half * 16;
        cpa16(adst,            gHs + asrc);
        cpa16(adst + APL,      gLs + asrc);
        cpa16(adst + 2 * APL,  gHr + asrc);
        cpa16(adst + 3 * APL,  gLr + asrc);
        cpa16(adst + 4 * APL,  gHi + asrc);
        cpa16(adst + 5 * APL,  gLi + asrc);
        int t = tid & 127, rb = t >> 1, hb = t & 1;
        int odd = tid >> 7;                         // 0: hi planes, 1: lo planes
        size_t bsrc = (size_t)(col0 + rb) * RK + k0 + hb * 8;
        uint32_t bdst = base + BOFF + odd * BPL + rb * 48 + hb * 16;
        cpa16(bdst,            odd ? (const void*)(gLr + bsrc) : (const void*)(gHr + bsrc));
        cpa16(bdst + 2 * BPL,  odd ? (const void*)(gLs + bsrc) : (const void*)(gHs + bsrc));
        cpa16(bdst + 4 * BPL,  odd ? (const void*)(gLd + bsrc) : (const void*)(gHd + bsrc));
    };

    float acc[3][4][2][4];
#pragma unroll
    for (int p = 0; p < 3; p++)
#pragma unroll
        for (int mf = 0; mf < 4; mf++)
#pragma unroll
            for (int nf = 0; nf < 2; nf++)
#pragma unroll
                for (int q = 0; q < 4; q++) acc[p][mf][nf][q] = 0.f;

    load_chunk(0, 0);  asm volatile("cp.async.commit_group;");
    load_chunk(1, 16); asm volatile("cp.async.commit_group;");
    load_chunk(2, 32); asm volatile("cp.async.commit_group;");

#pragma unroll 1
    for (int c = 0; c < 64; c++) {
        if (c + 3 < 64) load_chunk((c + 3) & 3, (c + 3) * 16);
        asm volatile("cp.async.commit_group;");
        asm volatile("cp.async.wait_group 3;");
        __syncthreads();

        uint32_t sb = smb + (c & 3) * STG;
#pragma unroll
        for (int p = 0; p < 3; p++) {
            uint32_t Ao = sb + (2 * p) * APL;
            uint32_t Bo = sb + BOFF + (2 * p) * BPL;
            uint32_t bh[4], bl[4];
            uint32_t baddr = Bo + (wn * 16 + lrow) * 48 + lhalf * 16;
            ldsm4(bh, baddr);
            ldsm4(bl, baddr + BPL);
#pragma unroll
            for (int mf = 0; mf < 4; mf++) {
                uint32_t ah[4], al[4];
                uint32_t aaddr = Ao + (wm * 64 + mf * 16 + lrow) * 48 + lhalf * 16;
                ldsm4(ah, aaddr);
                ldsm4(al, aaddr + APL);
                // nf0 uses (b[0], b[2]); nf1 uses (b[1], b[3])
                mma16(acc[p][mf][0], ah, bh[0], bh[2]);
                mma16(acc[p][mf][0], ah, bl[0], bl[2]);
                mma16(acc[p][mf][0], al, bh[0], bh[2]);
                mma16(acc[p][mf][1], ah, bh[1], bh[3]);
                mma16(acc[p][mf][1], ah, bl[1], bl[3]);
                mma16(acc[p][mf][1], al, bh[1], bh[3]);
            }
        }
        __syncthreads();
    }

    // ---- epilogue: re = k1 - k3, im = k1 - k2; write tile (+ mirror) ----
#pragma unroll
    for (int mf = 0; mf < 4; mf++)
#pragma unroll
        for (int nf = 0; nf < 2; nf++) {
            float re[4], im[4];
#pragma unroll
            for (int q = 0; q < 4; q++) {
                re[q] = acc[0][mf][nf][q] - acc[2][mf][nf][q];
                im[q] = acc[0][mf][nf][q] - acc[1][mf][nf][q];
            }
            unsigned r  = row0 + wm * 64 + mf * 16 + gid;
            unsigned cc = col0 + wn * 16 + nf * 8 + 2 * tig;
            gA_re[(size_t)r * D + cc]           = re[0];
            gA_re[(size_t)r * D + cc + 1]       = re[1];
            gA_re[(size_t)(r + 8) * D + cc]     = re[2];
            gA_re[(size_t)(r + 8) * D + cc + 1] = re[3];
            gA_im[(size_t)r * D + cc]           = im[0];
            gA_im[(size_t)r * D + cc + 1]       = im[1];
            gA_im[(size_t)(r + 8) * D + cc]     = im[2];
            gA_im[(size_t)(r + 8) * D + cc + 1] = im[3];
            if (mir) {
                gA_re[(size_t)cc * D + r]           = re[0];
                gA_re[(size_t)(cc + 1) * D + r]     = re[1];
                gA_re[(size_t)cc * D + r + 8]       = re[2];
                gA_re[(size_t)(cc + 1) * D + r + 8] = re[3];
                gA_im[(size_t)cc * D + r]           = -im[0];
                gA_im[(size_t)(cc + 1) * D + r]     = -im[1];
                gA_im[(size_t)cc * D + r + 8]       = -im[2];
                gA_im[(size_t)(cc + 1) * D + r + 8] = -im[3];
            }
        }
}

// ---------------------------------------------------------------------------
// trace: sum of re diagonal of rho -> 1/trace
// ---------------------------------------------------------------------------
__global__ void trace_kernel()
{
    __shared__ float red[256];
    float s = 0.f;
    for (int i = threadIdx.x; i < D; i += 256)
        s += gA_re[(size_t)i * D + i];
    red[threadIdx.x] = s;
    __syncthreads();
    for (int w = 128; w; w >>= 1) {
        if (threadIdx.x < w) red[threadIdx.x] += red[threadIdx.x + w];
        __syncthreads();
    }
    if (threadIdx.x == 0) g_inv_trace = 1.0f / red[0];
}

// ---------------------------------------------------------------------------
// Fused 2-qubit partial-trace sweep, factored into two 4-term complex stages.
//   out[(k,s1,s2), a, t] = sum M[s1,i1,j1] M[s2,i2,j2]
//                          * in[k, (2j1+j2)*rp + a, (2i1+i2)*cp + t]
// dir=0: A->B, dir=1: B->A. wim=0 skips imag store (last sweep).
// ---------------------------------------------------------------------------
__global__ void __launch_bounds__(256) qmt_sweep(int dir,
                                                 const float* __restrict__ Mr,
                                                 const float* __restrict__ Mi,
                                                 int lc, int wim)
{
    const float* __restrict__ in_re = dir ? gB_re : gA_re;
    const float* __restrict__ in_im = dir ? gB_im : gA_im;
    float* __restrict__ o_re = dir ? gA_re : gB_re;
    float* __restrict__ o_im = dir ? gA_im : gB_im;

    __shared__ float sr[16], si[16];   // M[s,i,j] at s*4+i*2+j
    int tid = threadIdx.x;
    if (tid < 16) { sr[tid] = Mr[tid]; si[tid] = Mi[tid]; }
    __syncthreads();

    unsigned gid = blockIdx.x * 256u + (unsigned)tid;   // 0 .. 2^20-1
    unsigned cp = 1u << lc;
    unsigned t = gid & (cp - 1u);
    unsigned a = (gid >> lc) & (cp - 1u);
    unsigned k = gid >> (2 * lc);
    unsigned base_in = k << (2 * lc + 4);

    float xr[16], xi[16];
#pragma unroll
    for (int J = 0; J < 4; J++)
#pragma unroll
        for (int I = 0; I < 4; I++) {
            unsigned off = base_in
                         + ((((unsigned)J << lc) + a) << (lc + 2))
                         + ((unsigned)I << lc) + t;
            xr[J * 4 + I] = in_re[off];
            xi[J * 4 + I] = in_im[off];
        }

    // stage 1: contract (j1,i1): y[s1][(j2,i2)]
    float yr[16], yi[16];
#pragma unroll
    for (int s1 = 0; s1 < 4; s1++)
#pragma unroll
        for (int j2 = 0; j2 < 2; j2++)
#pragma unroll
            for (int i2 = 0; i2 < 2; i2++) {
                float ar = 0.f, ai = 0.f;
#pragma unroll
                for (int j1 = 0; j1 < 2; j1++)
#pragma unroll
                    for (int i1 = 0; i1 < 2; i1++) {
                        float mr = sr[s1 * 4 + i1 * 2 + j1];
                        float mi = si[s1 * 4 + i1 * 2 + j1];
                        float vr = xr[(j1 * 2 + j2) * 4 + i1 * 2 + i2];
                        float vi = xi[(j1 * 2 + j2) * 4 + i1 * 2 + i2];
                        ar = fmaf(mr, vr, ar); ar = fmaf(-mi, vi, ar);
                        ai = fmaf(mr, vi, ai); ai = fmaf(mi, vr, ai);
                    }
                yr[s1 * 4 + j2 * 2 + i2] = ar;
                yi[s1 * 4 + j2 * 2 + i2] = ai;
            }

    // stage 2: contract (j2,i2)
#pragma unroll
    for (int s1 = 0; s1 < 4; s1++)
#pragma unroll
        for (int s2 = 0; s2 < 4; s2++) {
            float aR = 0.f, aI = 0.f;
#pragma unroll
            for (int j2 = 0; j2 < 2; j2++)
#pragma unroll
                for (int i2 = 0; i2 < 2; i2++) {
                    float mr = sr[s2 * 4 + i2 * 2 + j2];
                    float mi = si[s2 * 4 + i2 * 2 + j2];
                    float vr = yr[s1 * 4 + j2 * 2 + i2];
                    float vi = yi[s1 * 4 + j2 * 2 + i2];
                    aR = fmaf(mr, vr, aR); aR = fmaf(-mi, vi, aR);
                    aI = fmaf(mr, vi, aI); aI = fmaf(mi, vr, aI);
                }
            unsigned off = (((k << 4) + (unsigned)(s1 * 4 + s2)) << (2 * lc))
                         + (a << lc) + t;
            o_re[off] = aR;
            if (wim) o_im[off] = aI;
        }
}

// ---------------------------------------------------------------------------
// Gather: out[i] = P_all[idx[i]] / trace (real plane only; int32 indices).
// ---------------------------------------------------------------------------
__global__ void gather_kernel(const int* __restrict__ idx,
                              float* __restrict__ out, int n)
{
    int i = blockIdx.x * 256 + threadIdx.x;
    if (i < n) out[i] = gA_re[(unsigned)idx[i] & (NTOT - 1u)] * g_inv_trace;
}

// ---------------------------------------------------------------------------
extern "C" void kernel_launch(void* const* d_in, const int* in_sizes, int n_in,
                              void* d_out, int out_size)
{
    const float* params = (const float*)d_in[0];      // (2, 4096, 1024)
    const float* Mr = (const float*)d_in[1];          // (4,2,2)
    const float* Mi = (const float*)d_in[2];          // (4,2,2)
    const int* idx = (const int*)d_in[3];             // (1e6,) int32
    float* out = (float*)d_out;

    const float* Ur = params;
    const float* Ui = params + (size_t)D * RK;

    pack_split<<<16384, 256>>>(Ur, Ui);

    const int smem_bytes = 4 * STG;                   // 221184
    cudaFuncSetAttribute(gemm_mma,
                         cudaFuncAttributeMaxDynamicSharedMemorySize, smem_bytes);
    gemm_mma<<<1056, 256, smem_bytes>>>();

    trace_kernel<<<1, 256>>>();

    int dir = 0;
    for (int n = 1; n <= 6; n++) {
        qmt_sweep<<<4096, 256>>>(dir, Mr, Mi, 12 - 2 * n, n < 6 ? 1 : 0);
        dir ^= 1;
    }
    // final result (real plane) in gA_re

    int nq = in_sizes[3];
    gather_kernel<<<(nq + 255) / 256, 256>>>(idx, out, nq);
}

// round 7
// speedup vs baseline: 1.0316x; 1.0316x over previous
#include <cuda_runtime.h>
#include <cuda_bf16.h>
#include <stdint.h>
#include <math.h>

#define D    4096
#define RK   1024
#define NTOT (1u << 24)     // 4^12 probability entries

// GEMM smem geometry: K-chunk 16, pitch 48B, 8 planes, 4 stages
#define PIT  48
#define PLN  (128 * PIT)    // 6144 B per plane
#define STG  (8 * PLN)      // 49152 B per stage
#define NSTG 4
#define TPIT 132            // transpose pitch (floats)

// ---------------------------------------------------------------------------
// Scratch (__device__ globals per allocation rules).
// ---------------------------------------------------------------------------
__device__ float gA_re[NTOT];
__device__ float gA_im[NTOT];
__device__ float gB_re[NTOT];
__device__ float gB_im[NTOT];
__device__ __nv_bfloat16 gHr[(size_t)D * RK];   // hi(Ur)
__device__ __nv_bfloat16 gLr[(size_t)D * RK];   // lo(Ur)
__device__ __nv_bfloat16 gHi[(size_t)D * RK];   // hi(Ui)
__device__ __nv_bfloat16 gLi[(size_t)D * RK];   // lo(Ui)
__device__ float g_inv_trace;

// ---------------------------------------------------------------------------
static __device__ __forceinline__ void mma16(float c[4], const uint32_t a[4],
                                             uint32_t b0, uint32_t b1) {
    asm volatile(
        "mma.sync.aligned.m16n8k16.row.col.f32.bf16.bf16.f32 "
        "{%0,%1,%2,%3}, {%4,%5,%6,%7}, {%8,%9}, {%0,%1,%2,%3};\n"
        : "+f"(c[0]), "+f"(c[1]), "+f"(c[2]), "+f"(c[3])
        : "r"(a[0]), "r"(a[1]), "r"(a[2]), "r"(a[3]), "r"(b0), "r"(b1));
}
static __device__ __forceinline__ void ldsm4(uint32_t r[4], uint32_t addr) {
    asm volatile("ldmatrix.sync.aligned.m8n8.x4.shared.b16 {%0,%1,%2,%3}, [%4];"
                 : "=r"(r[0]), "=r"(r[1]), "=r"(r[2]), "=r"(r[3]) : "r"(addr));
}
static __device__ __forceinline__ void cpa16(uint32_t dst, const void* src) {
    asm volatile("cp.async.cg.shared.global [%0], [%1], 16;"
                 :: "r"(dst), "l"(src));
}

// ---------------------------------------------------------------------------
// Pack: hi = bf16(x), lo = bf16(x - hi). Launched 5x (blk0 offset) so the
// GEMM lands at launch index 5 for the ncu -s 5 capture window.
// ---------------------------------------------------------------------------
__global__ void __launch_bounds__(256) pack_split(const float* __restrict__ Ur,
                                                  const float* __restrict__ Ui,
                                                  int blk0)
{
    unsigned e = (blk0 + blockIdx.x) * 256u + threadIdx.x;
    if (e >= (unsigned)D * RK) return;
    float x = Ur[e];
    __nv_bfloat16 h = __float2bfloat16_rn(x);
    gHr[e] = h;
    gLr[e] = __float2bfloat16_rn(x - __bfloat162float(h));
    float y = Ui[e];
    __nv_bfloat16 h2 = __float2bfloat16_rn(y);
    gHi[e] = h2;
    gLi[e] = __float2bfloat16_rn(y - __bfloat162float(h2));
}

// ---------------------------------------------------------------------------
// rho = U U^H via bf16x3 mma.sync (m16n8k16). CTA tile 128x128, triangular
// grid (528 CTAs, bi>=bj), 8 warps (wm 2 x wn 4), warp tile 64x32.
// K-chunk 16, 4-stage cp.async pipeline, ldmatrix.x4 fragment loads.
// re = ArBr^T + AiBi^T ; im = AiBr^T - ArBi^T (minus via sign-flipped Ar).
// Split terms hh+hl+lh, ordered term-outermost for mma ILP.
// Mirror writes go through an smem transpose for gmem coalescing.
// ---------------------------------------------------------------------------
__global__ void __launch_bounds__(256, 1) gemm_mma()
{
    extern __shared__ char sm[];
    const uint32_t smb = (uint32_t)__cvta_generic_to_shared(sm);

    const int tid  = threadIdx.x;
    const int lane = tid & 31;
    const int wid  = tid >> 5;
    const int gid  = lane >> 2;     // 0..7
    const int tig  = lane & 3;      // 0..3
    const int wm   = wid >> 2;      // 0..1
    const int wn   = wid & 3;       // 0..3
    const int lrow = lane & 15;
    const int lh16 = (lane >> 4) * 16;

    // triangular tile index
    int l = blockIdx.x;
    int bi = (int)((sqrtf(8.0f * (float)l + 1.0f) - 1.0f) * 0.5f);
    while ((bi + 1) * (bi + 2) / 2 <= l) bi++;
    while (bi * (bi + 1) / 2 > l) bi--;
    int bj = l - bi * (bi + 1) / 2;
    const int row0 = bi * 128, col0 = bj * 128;

    // plane order: 0 A-Hr, 1 A-Lr, 2 A-Hi, 3 A-Li, 4 B-Hr, 5 B-Lr, 6 B-Hi, 7 B-Li
    auto load_chunk = [&](int stg, int k0) {
        uint32_t base = smb + stg * STG;
        int r = tid >> 1, h = tid & 1;
        size_t arow = (size_t)(row0 + r) * RK + k0 + h * 8;
        size_t brow = (size_t)(col0 + r) * RK + k0 + h * 8;
        uint32_t ad = base + r * PIT + h * 16;
        cpa16(ad,           gHr + arow);
        cpa16(ad + PLN,     gLr + arow);
        cpa16(ad + 2 * PLN, gHi + arow);
        cpa16(ad + 3 * PLN, gLi + arow);
        cpa16(ad + 4 * PLN, gHr + brow);
        cpa16(ad + 5 * PLN, gLr + brow);
        cpa16(ad + 6 * PLN, gHi + brow);
        cpa16(ad + 7 * PLN, gLi + brow);
    };

    float accre[4][4][4], accim[4][4][4];
#pragma unroll
    for (int a = 0; a < 4; a++)
#pragma unroll
        for (int b = 0; b < 4; b++)
#pragma unroll
            for (int q = 0; q < 4; q++) { accre[a][b][q] = 0.f; accim[a][b][q] = 0.f; }

    load_chunk(0, 0);  asm volatile("cp.async.commit_group;");
    load_chunk(1, 16); asm volatile("cp.async.commit_group;");
    load_chunk(2, 32); asm volatile("cp.async.commit_group;");

    // B frag selector: nf -> (reg, reg+2) within 8-reg plane arrays
#define BSEL(P, nf) P[((nf) & 1) + ((nf) >> 1) * 4], P[((nf) & 1) + ((nf) >> 1) * 4 + 2]

#pragma unroll 1
    for (int c = 0; c < 64; c++) {
        if (c + 3 < 64) load_chunk((c + 3) & 3, (c + 3) * 16);
        asm volatile("cp.async.commit_group;");
        asm volatile("cp.async.wait_group 3;");
        __syncthreads();

        uint32_t sb = smb + (c & 3) * STG;

        // ---- B fragments: 4 planes x 8 regs ----
        uint32_t BrH[8], BrL[8], BiH[8], BiL[8];
        {
            uint32_t b0 = sb + (wn * 32 + lrow) * PIT + lh16;
            uint32_t b1 = sb + (wn * 32 + 16 + lrow) * PIT + lh16;
            ldsm4(BrH,     b0 + 4 * PLN); ldsm4(BrH + 4, b1 + 4 * PLN);
            ldsm4(BrL,     b0 + 5 * PLN); ldsm4(BrL + 4, b1 + 5 * PLN);
            ldsm4(BiH,     b0 + 6 * PLN); ldsm4(BiH + 4, b1 + 6 * PLN);
            ldsm4(BiL,     b0 + 7 * PLN); ldsm4(BiL + 4, b1 + 7 * PLN);
        }

        uint32_t AH[4][4], AL[4][4];
        // ---- plane Ar ----
#pragma unroll
        for (int mf = 0; mf < 4; mf++) {
            uint32_t a0 = sb + (wm * 64 + mf * 16 + lrow) * PIT + lh16;
            ldsm4(AH[mf], a0);
            ldsm4(AL[mf], a0 + PLN);
        }
        // re += Ar*Br, term-outermost (hh, hl, lh)
#pragma unroll
        for (int mf = 0; mf < 4; mf++)
#pragma unroll
            for (int nf = 0; nf < 4; nf++) mma16(accre[mf][nf], AH[mf], BSEL(BrH, nf));
#pragma unroll
        for (int mf = 0; mf < 4; mf++)
#pragma unroll
            for (int nf = 0; nf < 4; nf++) mma16(accre[mf][nf], AH[mf], BSEL(BrL, nf));
#pragma unroll
        for (int mf = 0; mf < 4; mf++)
#pragma unroll
            for (int nf = 0; nf < 4; nf++) mma16(accre[mf][nf], AL[mf], BSEL(BrH, nf));
        // im += (-Ar)*Bi (exact sign flip)
#pragma unroll
        for (int mf = 0; mf < 4; mf++)
#pragma unroll
            for (int q = 0; q < 4; q++) { AH[mf][q] ^= 0x80008000u; AL[mf][q] ^= 0x80008000u; }
#pragma unroll
        for (int mf = 0; mf < 4; mf++)
#pragma unroll
            for (int nf = 0; nf < 4; nf++) mma16(accim[mf][nf], AH[mf], BSEL(BiH, nf));
#pragma unroll
        for (int mf = 0; mf < 4; mf++)
#pragma unroll
            for (int nf = 0; nf < 4; nf++) mma16(accim[mf][nf], AH[mf], BSEL(BiL, nf));
#pragma unroll
        for (int mf = 0; mf < 4; mf++)
#pragma unroll
            for (int nf = 0; nf < 4; nf++) mma16(accim[mf][nf], AL[mf], BSEL(BiH, nf));
        // ---- plane Ai ----
#pragma unroll
        for (int mf = 0; mf < 4; mf++) {
            uint32_t a0 = sb + 2 * PLN + (wm * 64 + mf * 16 + lrow) * PIT + lh16;
            ldsm4(AH[mf], a0);
            ldsm4(AL[mf], a0 + PLN);
        }
        // re += Ai*Bi
#pragma unroll
        for (int mf = 0; mf < 4; mf++)
#pragma unroll
            for (int nf = 0; nf < 4; nf++) mma16(accre[mf][nf], AH[mf], BSEL(BiH, nf));
#pragma unroll
        for (int mf = 0; mf < 4; mf++)
#pragma unroll
            for (int nf = 0; nf < 4; nf++) mma16(accre[mf][nf], AH[mf], BSEL(BiL, nf));
#pragma unroll
        for (int mf = 0; mf < 4; mf++)
#pragma unroll
            for (int nf = 0; nf < 4; nf++) mma16(accre[mf][nf], AL[mf], BSEL(BiH, nf));
        // im += Ai*Br
#pragma unroll
        for (int mf = 0; mf < 4; mf++)
#pragma unroll
            for (int nf = 0; nf < 4; nf++) mma16(accim[mf][nf], AH[mf], BSEL(BrH, nf));
#pragma unroll
        for (int mf = 0; mf < 4; mf++)
#pragma unroll
            for (int nf = 0; nf < 4; nf++) mma16(accim[mf][nf], AH[mf], BSEL(BrL, nf));
#pragma unroll
        for (int mf = 0; mf < 4; mf++)
#pragma unroll
            for (int nf = 0; nf < 4; nf++) mma16(accim[mf][nf], AL[mf], BSEL(BrH, nf));

        __syncthreads();
    }
#undef BSEL

    // drain pipeline before reusing smem
    asm volatile("cp.async.wait_group 0;");
    __syncthreads();

    // ---- direct tile writes (coalesced enough: 8B/lane, 32B sectors) ----
#pragma unroll
    for (int mf = 0; mf < 4; mf++)
#pragma unroll
        for (int nf = 0; nf < 4; nf++) {
            unsigned r  = row0 + wm * 64 + mf * 16 + gid;
            unsigned cc = col0 + wn * 32 + nf * 8 + 2 * tig;
            const float* cr = accre[mf][nf];
            const float* ci = accim[mf][nf];
            *(float2*)&gA_re[(size_t)r * D + cc]       = make_float2(cr[0], cr[1]);
            *(float2*)&gA_re[(size_t)(r + 8) * D + cc] = make_float2(cr[2], cr[3]);
            *(float2*)&gA_im[(size_t)r * D + cc]       = make_float2(ci[0], ci[1]);
            *(float2*)&gA_im[(size_t)(r + 8) * D + cc] = make_float2(ci[2], ci[3]);
        }

    // ---- mirror writes via smem transpose (coalesced) ----
    if (bi != bj) {
        float* smf = (float*)sm;    // 128 x TPIT floats (67584 B)
        // plane 0: re (mirror value = re), plane 1: im (mirror value = -im)
#pragma unroll 1
        for (int pl = 0; pl < 2; pl++) {
#pragma unroll
            for (int mf = 0; mf < 4; mf++)
#pragma unroll
                for (int nf = 0; nf < 4; nf++) {
                    int rL  = wm * 64 + mf * 16 + gid;
                    int ccL = wn * 32 + nf * 8 + 2 * tig;
                    const float* v = pl ? accim[mf][nf] : accre[mf][nf];
                    float s = pl ? -1.f : 1.f;
                    smf[(ccL)     * TPIT + rL]     = s * v[0];
                    smf[(ccL + 1) * TPIT + rL]     = s * v[1];
                    smf[(ccL)     * TPIT + rL + 8] = s * v[2];
                    smf[(ccL + 1) * TPIT + rL + 8] = s * v[3];
                }
            __syncthreads();
            float* gout = pl ? gA_im : gA_re;
            // each warp: 16 mirror rows; per row, 32 lanes write float4 (512B)
#pragma unroll
            for (int r8 = 0; r8 < 16; r8++) {
                int mr = wid * 16 + r8;
                float4 v = *(float4*)&smf[mr * TPIT + lane * 4];
                *(float4*)&gout[(size_t)(col0 + mr) * D + row0 + lane * 4] = v;
            }
            __syncthreads();
        }
    }
}

// ---------------------------------------------------------------------------
// trace: sum of re diagonal of rho -> 1/trace
// ---------------------------------------------------------------------------
__global__ void trace_kernel()
{
    __shared__ float red[256];
    float s = 0.f;
    for (int i = threadIdx.x; i < D; i += 256)
        s += gA_re[(size_t)i * D + i];
    red[threadIdx.x] = s;
    __syncthreads();
    for (int w = 128; w; w >>= 1) {
        if (threadIdx.x < w) red[threadIdx.x] += red[threadIdx.x + w];
        __syncthreads();
    }
    if (threadIdx.x == 0) g_inv_trace = 1.0f / red[0];
}

// ---------------------------------------------------------------------------
// Fused 2-qubit partial-trace sweep, factored into two 4-term complex stages.
// dir=0: A->B, dir=1: B->A. wim=0 skips imag store (last sweep).
// ---------------------------------------------------------------------------
__global__ void __launch_bounds__(256) qmt_sweep(int dir,
                                                 const float* __restrict__ Mr,
                                                 const float* __restrict__ Mi,
                                                 int lc, int wim)
{
    const float* __restrict__ in_re = dir ? gB_re : gA_re;
    const float* __restrict__ in_im = dir ? gB_im : gA_im;
    float* __restrict__ o_re = dir ? gA_re : gB_re;
    float* __restrict__ o_im = dir ? gA_im : gB_im;

    __shared__ float sr[16], si[16];   // M[s,i,j] at s*4+i*2+j
    int tid = threadIdx.x;
    if (tid < 16) { sr[tid] = Mr[tid]; si[tid] = Mi[tid]; }
    __syncthreads();

    unsigned gid = blockIdx.x * 256u + (unsigned)tid;   // 0 .. 2^20-1
    unsigned cp = 1u << lc;
    unsigned t = gid & (cp - 1u);
    unsigned a = (gid >> lc) & (cp - 1u);
    unsigned k = gid >> (2 * lc);
    unsigned base_in = k << (2 * lc + 4);

    float xr[16], xi[16];
#pragma unroll
    for (int J = 0; J < 4; J++)
#pragma unroll
        for (int I = 0; I < 4; I++) {
            unsigned off = base_in
                         + ((((unsigned)J << lc) + a) << (lc + 2))
                         + ((unsigned)I << lc) + t;
            xr[J * 4 + I] = in_re[off];
            xi[J * 4 + I] = in_im[off];
        }

    // stage 1: contract (j1,i1): y[s1][(j2,i2)]
    float yr[16], yi[16];
#pragma unroll
    for (int s1 = 0; s1 < 4; s1++)
#pragma unroll
        for (int j2 = 0; j2 < 2; j2++)
#pragma unroll
            for (int i2 = 0; i2 < 2; i2++) {
                float ar = 0.f, ai = 0.f;
#pragma unroll
                for (int j1 = 0; j1 < 2; j1++)
#pragma unroll
                    for (int i1 = 0; i1 < 2; i1++) {
                        float mr = sr[s1 * 4 + i1 * 2 + j1];
                        float mi = si[s1 * 4 + i1 * 2 + j1];
                        float vr = xr[(j1 * 2 + j2) * 4 + i1 * 2 + i2];
                        float vi = xi[(j1 * 2 + j2) * 4 + i1 * 2 + i2];
                        ar = fmaf(mr, vr, ar); ar = fmaf(-mi, vi, ar);
                        ai = fmaf(mr, vi, ai); ai = fmaf(mi, vr, ai);
                    }
                yr[s1 * 4 + j2 * 2 + i2] = ar;
                yi[s1 * 4 + j2 * 2 + i2] = ai;
            }

    // stage 2: contract (j2,i2)
#pragma unroll
    for (int s1 = 0; s1 < 4; s1++)
#pragma unroll
        for (int s2 = 0; s2 < 4; s2++) {
            float aR = 0.f, aI = 0.f;
#pragma unroll
            for (int j2 = 0; j2 < 2; j2++)
#pragma unroll
                for (int i2 = 0; i2 < 2; i2++) {
                    float mr = sr[s2 * 4 + i2 * 2 + j2];
                    float mi = si[s2 * 4 + i2 * 2 + j2];
                    float vr = yr[s1 * 4 + j2 * 2 + i2];
                    float vi = yi[s1 * 4 + j2 * 2 + i2];
                    aR = fmaf(mr, vr, aR); aR = fmaf(-mi, vi, aR);
                    aI = fmaf(mr, vi, aI); aI = fmaf(mi, vr, aI);
                }
            unsigned off = (((k << 4) + (unsigned)(s1 * 4 + s2)) << (2 * lc))
                         + (a << lc) + t;
            o_re[off] = aR;
            if (wim) o_im[off] = aI;
        }
}

// ---------------------------------------------------------------------------
// Gather: out[i] = P_all[idx[i]] / trace (real plane only; int32 indices).
// ---------------------------------------------------------------------------
__global__ void gather_kernel(const int* __restrict__ idx,
                              float* __restrict__ out, int n)
{
    int i = blockIdx.x * 256 + threadIdx.x;
    if (i < n) out[i] = gA_re[(unsigned)idx[i] & (NTOT - 1u)] * g_inv_trace;
}

// ---------------------------------------------------------------------------
extern "C" void kernel_launch(void* const* d_in, const int* in_sizes, int n_in,
                              void* d_out, int out_size)
{
    const float* params = (const float*)d_in[0];      // (2, 4096, 1024)
    const float* Mr = (const float*)d_in[1];          // (4,2,2)
    const float* Mi = (const float*)d_in[2];          // (4,2,2)
    const int* idx = (const int*)d_in[3];             // (1e6,) int32
    float* out = (float*)d_out;

    const float* Ur = params;
    const float* Ui = params + (size_t)D * RK;

    // 5 pack launches (indices 0-4) so gemm_mma is launch index 5 for ncu -s 5.
    const int total_blocks = 16384;
    const int per = (total_blocks + 4) / 5;           // 3277
    for (int p = 0; p < 5; p++) {
        int b0 = p * per;
        int nb = (b0 + per <= total_blocks) ? per : (total_blocks - b0);
        pack_split<<<nb, 256>>>(Ur, Ui, b0);
    }

    const int smem_bytes = NSTG * STG;                // 196608
    cudaFuncSetAttribute(gemm_mma,
                         cudaFuncAttributeMaxDynamicSharedMemorySize, smem_bytes);
    gemm_mma<<<528, 256, smem_bytes>>>();

    trace_kernel<<<1, 256>>>();

    int dir = 0;
    for (int n = 1; n <= 6; n++) {
        qmt_sweep<<<4096, 256>>>(dir, Mr, Mi, 12 - 2 * n, n < 6 ? 1 : 0);
        dir ^= 1;
    }
    // final result (real plane) in gA_re

    int nq = in_sizes[3];
    gather_kernel<<<(nq + 255) / 256, 256>>>(idx, out, nq);
}

// round 8
// speedup vs baseline: 1.2563x; 1.2178x over previous
#include <cuda_runtime.h>
#include <cuda_bf16.h>
#include <stdint.h>
#include <math.h>

#define D    4096
#define RK   1024
#define NTOT (1u << 24)     // 4^12 probability entries
#define PITB 80             // smem row pitch in BYTES (40 bf16) — conflict-free
#define TPIT 132            // epilogue transpose pitch (floats)

// ---------------------------------------------------------------------------
// Scratch (__device__ globals per allocation rules).
// ---------------------------------------------------------------------------
__device__ float gA_re[NTOT];
__device__ float gA_im[NTOT];
__device__ float gB_re[NTOT];
__device__ float gB_im[NTOT];
__device__ __nv_bfloat16 gHr[(size_t)D * RK];   // hi(Ur)
__device__ __nv_bfloat16 gLr[(size_t)D * RK];   // lo(Ur)
__device__ __nv_bfloat16 gHi[(size_t)D * RK];   // hi(Ui)
__device__ __nv_bfloat16 gLi[(size_t)D * RK];   // lo(Ui)
__device__ float g_inv_trace;

// ---------------------------------------------------------------------------
static __device__ __forceinline__ void mma16(float c[4], const uint32_t a[4],
                                             const uint32_t b[2]) {
    asm volatile(
        "mma.sync.aligned.m16n8k16.row.col.f32.bf16.bf16.f32 "
        "{%0,%1,%2,%3}, {%4,%5,%6,%7}, {%8,%9}, {%0,%1,%2,%3};\n"
        : "+f"(c[0]), "+f"(c[1]), "+f"(c[2]), "+f"(c[3])
        : "r"(a[0]), "r"(a[1]), "r"(a[2]), "r"(a[3]), "r"(b[0]), "r"(b[1]));
}
static __device__ __forceinline__ uint32_t lds32(const char* base, int off) {
    return *(const uint32_t*)(base + off);
}

// ---------------------------------------------------------------------------
// Pack: hi = bf16(x), lo = bf16(x - hi) for both planes of U.
// ---------------------------------------------------------------------------
__global__ void __launch_bounds__(256) pack_split(const float* __restrict__ Ur,
                                                  const float* __restrict__ Ui)
{
    unsigned e = blockIdx.x * 256u + threadIdx.x;   // 0 .. 4M-1
    float x = Ur[e];
    __nv_bfloat16 h = __float2bfloat16_rn(x);
    gHr[e] = h;
    gLr[e] = __float2bfloat16_rn(x - __bfloat162float(h));
    float y = Ui[e];
    __nv_bfloat16 h2 = __float2bfloat16_rn(y);
    gHi[e] = h2;
    gLi[e] = __float2bfloat16_rn(y - __bfloat162float(h2));
}

// ---------------------------------------------------------------------------
// rho = U U^H via bf16x3 mma.sync (m16n8k16). Tile 128x128, triangular grid
// (528 CTAs, bi>=bj). K-chunk 32, double-buffered cp.async; 8 smem planes per
// stage: {Ar,Ai,Br,Bi} x {hi,lo}, rows pitched at 80B.  (R5 mainloop, proven.)
// re = ArBr^T + AiBi^T ; im = AiBr^T - ArBi^T (minus via sign-flipped Ar).
// Split products kept: hh + hl + lh (lo*lo dropped).
// Epilogue: main tile via float2; mirror tile via smem transpose (coalesced).
// ---------------------------------------------------------------------------
__global__ void __launch_bounds__(256, 1) gemm_mma()
{
    extern __shared__ char sm[];    // 2 stages * 8 planes * 128*PITB bytes

    const int tid  = threadIdx.x;
    const int lane = tid & 31;
    const int wid  = tid >> 5;
    const int gid  = lane >> 2;     // 0..7
    const int tig  = lane & 3;      // 0..3
    const int wm   = wid >> 2;      // 0..1
    const int wn   = wid & 3;       // 0..3

    // triangular tile index
    int l = blockIdx.x;
    int bi = (int)((sqrtf(8.0f * (float)l + 1.0f) - 1.0f) * 0.5f);
    while ((bi + 1) * (bi + 2) / 2 <= l) bi++;
    while (bi * (bi + 1) / 2 > l) bi--;
    int bj = l - bi * (bi + 1) / 2;
    const int row0 = bi * 128, col0 = bj * 128;

    const int PLNB = 128 * PITB;    // 10240 B per plane
    const int BUFB = 8 * PLNB;      // 81920 B per stage

    // plane order: 0 ArH, 1 ArL, 2 AiH, 3 AiL, 4 BrH, 5 BrL, 6 BiH, 7 BiL
    auto load_chunk = [&](int buf, int k0) {
        char* base = sm + buf * BUFB;
#pragma unroll
        for (int u = 0; u < 16; u++) {
            int i = tid + u * 256;          // 0..4095 16B slots
            int plane = i >> 9;             // 0..7
            int rem = i & 511;
            int r = rem >> 2;               // 0..127
            int q = rem & 3;                // 16B slot within 64B row-chunk
            const __nv_bfloat16* arr =
                (plane == 0 || plane == 4) ? gHr :
                (plane == 1 || plane == 5) ? gLr :
                (plane == 2 || plane == 6) ? gHi : gLi;
            int baser = (plane < 4) ? row0 : col0;
            const __nv_bfloat16* src =
                arr + (size_t)(baser + r) * RK + k0 + q * 8;
            uint32_t dst = (uint32_t)__cvta_generic_to_shared(
                base + plane * PLNB + r * PITB + q * 16);
            asm volatile("cp.async.cg.shared.global [%0], [%1], 16;"
                         :: "r"(dst), "l"(src));
        }
    };

    float accre[4][4][4], accim[4][4][4];
#pragma unroll
    for (int a = 0; a < 4; a++)
#pragma unroll
        for (int b = 0; b < 4; b++)
#pragma unroll
            for (int q = 0; q < 4; q++) { accre[a][b][q] = 0.f; accim[a][b][q] = 0.f; }

    load_chunk(0, 0);
    asm volatile("cp.async.commit_group;");

#pragma unroll 1
    for (int c = 0; c < 32; c++) {
        if (c + 1 < 32) load_chunk((c + 1) & 1, (c + 1) * 32);
        asm volatile("cp.async.commit_group;");
        asm volatile("cp.async.wait_group 1;");
        __syncthreads();

        const char* bb = sm + (c & 1) * BUFB;

#pragma unroll
        for (int kk = 0; kk < 2; kk++) {      // two k16 halves of the 32-chunk
            const int kbyte = kk * 32 + tig * 4;   // within-row byte offset

            // ---- B fragments: BrH, BrL, BiH, BiL (2 regs x 4 nf each) ----
            uint32_t BrH[4][2], BrL[4][2], BiH[4][2], BiL[4][2];
#pragma unroll
            for (int nf = 0; nf < 4; nf++) {
                int n = (wn * 32 + nf * 8 + gid) * PITB;
                BrH[nf][0] = lds32(bb + 4 * PLNB, n + kbyte);
                BrH[nf][1] = lds32(bb + 4 * PLNB, n + kbyte + 16);
                BrL[nf][0] = lds32(bb + 5 * PLNB, n + kbyte);
                BrL[nf][1] = lds32(bb + 5 * PLNB, n + kbyte + 16);
                BiH[nf][0] = lds32(bb + 6 * PLNB, n + kbyte);
                BiH[nf][1] = lds32(bb + 6 * PLNB, n + kbyte + 16);
                BiL[nf][0] = lds32(bb + 7 * PLNB, n + kbyte);
                BiL[nf][1] = lds32(bb + 7 * PLNB, n + kbyte + 16);
            }

            uint32_t AH[4][4], AL[4][4];
            // ---- plane Ar (hi/lo) ----
#pragma unroll
            for (int mf = 0; mf < 4; mf++) {
                int r = (wm * 64 + mf * 16 + gid) * PITB;
                AH[mf][0] = lds32(bb,        r + kbyte);
                AH[mf][1] = lds32(bb,        r + 8 * PITB + kbyte);
                AH[mf][2] = lds32(bb,        r + kbyte + 16);
                AH[mf][3] = lds32(bb,        r + 8 * PITB + kbyte + 16);
                AL[mf][0] = lds32(bb + PLNB, r + kbyte);
                AL[mf][1] = lds32(bb + PLNB, r + 8 * PITB + kbyte);
                AL[mf][2] = lds32(bb + PLNB, r + kbyte + 16);
                AL[mf][3] = lds32(bb + PLNB, r + 8 * PITB + kbyte + 16);
            }
            // re += Ar*Br (hh, hl, lh)
#pragma unroll
            for (int mf = 0; mf < 4; mf++)
#pragma unroll
                for (int nf = 0; nf < 4; nf++) {
                    mma16(accre[mf][nf], AH[mf], BrH[nf]);
                    mma16(accre[mf][nf], AH[mf], BrL[nf]);
                    mma16(accre[mf][nf], AL[mf], BrH[nf]);
                }
            // im += (-Ar)*Bi  (exact sign flip of both bf16 halves)
#pragma unroll
            for (int mf = 0; mf < 4; mf++)
#pragma unroll
                for (int q = 0; q < 4; q++) {
                    AH[mf][q] ^= 0x80008000u;
                    AL[mf][q] ^= 0x80008000u;
                }
#pragma unroll
            for (int mf = 0; mf < 4; mf++)
#pragma unroll
                for (int nf = 0; nf < 4; nf++) {
                    mma16(accim[mf][nf], AH[mf], BiH[nf]);
                    mma16(accim[mf][nf], AH[mf], BiL[nf]);
                    mma16(accim[mf][nf], AL[mf], BiH[nf]);
                }
            // ---- plane Ai (hi/lo) ----
#pragma unroll
            for (int mf = 0; mf < 4; mf++) {
                int r = (wm * 64 + mf * 16 + gid) * PITB;
                AH[mf][0] = lds32(bb + 2 * PLNB, r + kbyte);
                AH[mf][1] = lds32(bb + 2 * PLNB, r + 8 * PITB + kbyte);
                AH[mf][2] = lds32(bb + 2 * PLNB, r + kbyte + 16);
                AH[mf][3] = lds32(bb + 2 * PLNB, r + 8 * PITB + kbyte + 16);
                AL[mf][0] = lds32(bb + 3 * PLNB, r + kbyte);
                AL[mf][1] = lds32(bb + 3 * PLNB, r + 8 * PITB + kbyte);
                AL[mf][2] = lds32(bb + 3 * PLNB, r + kbyte + 16);
                AL[mf][3] = lds32(bb + 3 * PLNB, r + 8 * PITB + kbyte + 16);
            }
            // re += Ai*Bi
#pragma unroll
            for (int mf = 0; mf < 4; mf++)
#pragma unroll
                for (int nf = 0; nf < 4; nf++) {
                    mma16(accre[mf][nf], AH[mf], BiH[nf]);
                    mma16(accre[mf][nf], AH[mf], BiL[nf]);
                    mma16(accre[mf][nf], AL[mf], BiH[nf]);
                }
            // im += Ai*Br
#pragma unroll
            for (int mf = 0; mf < 4; mf++)
#pragma unroll
                for (int nf = 0; nf < 4; nf++) {
                    mma16(accim[mf][nf], AH[mf], BrH[nf]);
                    mma16(accim[mf][nf], AH[mf], BrL[nf]);
                    mma16(accim[mf][nf], AL[mf], BrH[nf]);
                }
        }
        __syncthreads();
    }

    // drain cp.async before reusing smem for the transpose
    asm volatile("cp.async.wait_group 0;");
    __syncthreads();

    // ---- main tile writes (row-major, float2 per store) ----
#pragma unroll
    for (int mf = 0; mf < 4; mf++)
#pragma unroll
        for (int nf = 0; nf < 4; nf++) {
            unsigned r  = row0 + wm * 64 + mf * 16 + gid;
            unsigned cc = col0 + wn * 32 + nf * 8 + 2 * tig;
            const float* cr = accre[mf][nf];
            const float* ci = accim[mf][nf];
            *(float2*)&gA_re[(size_t)r * D + cc]       = make_float2(cr[0], cr[1]);
            *(float2*)&gA_re[(size_t)(r + 8) * D + cc] = make_float2(cr[2], cr[3]);
            *(float2*)&gA_im[(size_t)r * D + cc]       = make_float2(ci[0], ci[1]);
            *(float2*)&gA_im[(size_t)(r + 8) * D + cc] = make_float2(ci[2], ci[3]);
        }

    // ---- mirror writes via smem transpose (coalesced 512B rows) ----
    if (bi != bj) {
        float* smf = (float*)sm;    // 128 x TPIT floats = 67584 B (< smem)
#pragma unroll 1
        for (int pl = 0; pl < 2; pl++) {
            float sgn = pl ? -1.f : 1.f;
#pragma unroll
            for (int mf = 0; mf < 4; mf++)
#pragma unroll
                for (int nf = 0; nf < 4; nf++) {
                    int rL  = wm * 64 + mf * 16 + gid;
                    int ccL = wn * 32 + nf * 8 + 2 * tig;
                    const float* v = pl ? accim[mf][nf] : accre[mf][nf];
                    smf[(ccL)     * TPIT + rL]     = sgn * v[0];
                    smf[(ccL + 1) * TPIT + rL]     = sgn * v[1];
                    smf[(ccL)     * TPIT + rL + 8] = sgn * v[2];
                    smf[(ccL + 1) * TPIT + rL + 8] = sgn * v[3];
                }
            __syncthreads();
            float* gout = pl ? gA_im : gA_re;
#pragma unroll
            for (int r8 = 0; r8 < 16; r8++) {
                int mr = wid * 16 + r8;
                float4 v = *(float4*)&smf[mr * TPIT + lane * 4];
                *(float4*)&gout[(size_t)(col0 + mr) * D + row0 + lane * 4] = v;
            }
            __syncthreads();
        }
    }
}

// ---------------------------------------------------------------------------
// trace: sum of re diagonal of rho -> 1/trace
// ---------------------------------------------------------------------------
__global__ void trace_kernel()
{
    __shared__ float red[256];
    float s = 0.f;
    for (int i = threadIdx.x; i < D; i += 256)
        s += gA_re[(size_t)i * D + i];
    red[threadIdx.x] = s;
    __syncthreads();
    for (int w = 128; w; w >>= 1) {
        if (threadIdx.x < w) red[threadIdx.x] += red[threadIdx.x + w];
        __syncthreads();
    }
    if (threadIdx.x == 0) g_inv_trace = 1.0f / red[0];
}

// ---------------------------------------------------------------------------
// Fused 2-qubit partial-trace sweep, factored into two 4-term complex stages.
// dir=0: A->B, dir=1: B->A. wim=0 skips imag store (last sweep).
// ---------------------------------------------------------------------------
__global__ void __launch_bounds__(256) qmt_sweep(int dir,
                                                 const float* __restrict__ Mr,
                                                 const float* __restrict__ Mi,
                                                 int lc, int wim)
{
    const float* __restrict__ in_re = dir ? gB_re : gA_re;
    const float* __restrict__ in_im = dir ? gB_im : gA_im;
    float* __restrict__ o_re = dir ? gA_re : gB_re;
    float* __restrict__ o_im = dir ? gA_im : gB_im;

    __shared__ float sr[16], si[16];   // M[s,i,j] at s*4+i*2+j
    int tid = threadIdx.x;
    if (tid < 16) { sr[tid] = Mr[tid]; si[tid] = Mi[tid]; }
    __syncthreads();

    unsigned gid = blockIdx.x * 256u + (unsigned)tid;   // 0 .. 2^20-1
    unsigned cp = 1u << lc;
    unsigned t = gid & (cp - 1u);
    unsigned a = (gid >> lc) & (cp - 1u);
    unsigned k = gid >> (2 * lc);
    unsigned base_in = k << (2 * lc + 4);

    float xr[16], xi[16];
#pragma unroll
    for (int J = 0; J < 4; J++)
#pragma unroll
        for (int I = 0; I < 4; I++) {
            unsigned off = base_in
                         + ((((unsigned)J << lc) + a) << (lc + 2))
                         + ((unsigned)I << lc) + t;
            xr[J * 4 + I] = in_re[off];
            xi[J * 4 + I] = in_im[off];
        }

    // stage 1: contract (j1,i1): y[s1][(j2,i2)]
    float yr[16], yi[16];
#pragma unroll
    for (int s1 = 0; s1 < 4; s1++)
#pragma unroll
        for (int j2 = 0; j2 < 2; j2++)
#pragma unroll
            for (int i2 = 0; i2 < 2; i2++) {
                float ar = 0.f, ai = 0.f;
#pragma unroll
                for (int j1 = 0; j1 < 2; j1++)
#pragma unroll
                    for (int i1 = 0; i1 < 2; i1++) {
                        float mr = sr[s1 * 4 + i1 * 2 + j1];
                        float mi = si[s1 * 4 + i1 * 2 + j1];
                        float vr = xr[(j1 * 2 + j2) * 4 + i1 * 2 + i2];
                        float vi = xi[(j1 * 2 + j2) * 4 + i1 * 2 + i2];
                        ar = fmaf(mr, vr, ar); ar = fmaf(-mi, vi, ar);
                        ai = fmaf(mr, vi, ai); ai = fmaf(mi, vr, ai);
                    }
                yr[s1 * 4 + j2 * 2 + i2] = ar;
                yi[s1 * 4 + j2 * 2 + i2] = ai;
            }

    // stage 2: contract (j2,i2)
#pragma unroll
    for (int s1 = 0; s1 < 4; s1++)
#pragma unroll
        for (int s2 = 0; s2 < 4; s2++) {
            float aR = 0.f, aI = 0.f;
#pragma unroll
            for (int j2 = 0; j2 < 2; j2++)
#pragma unroll
                for (int i2 = 0; i2 < 2; i2++) {
                    float mr = sr[s2 * 4 + i2 * 2 + j2];
                    float mi = si[s2 * 4 + i2 * 2 + j2];
                    float vr = yr[s1 * 4 + j2 * 2 + i2];
                    float vi = yi[s1 * 4 + j2 * 2 + i2];
                    aR = fmaf(mr, vr, aR); aR = fmaf(-mi, vi, aR);
                    aI = fmaf(mr, vi, aI); aI = fmaf(mi, vr, aI);
                }
            unsigned off = (((k << 4) + (unsigned)(s1 * 4 + s2)) << (2 * lc))
                         + (a << lc) + t;
            o_re[off] = aR;
            if (wim) o_im[off] = aI;
        }
}

// ---------------------------------------------------------------------------
// Gather: out[i] = P_all[idx[i]] / trace (real plane only; int32 indices).
// ---------------------------------------------------------------------------
__global__ void gather_kernel(const int* __restrict__ idx,
                              float* __restrict__ out, int n)
{
    int i = blockIdx.x * 256 + threadIdx.x;
    if (i < n) out[i] = gA_re[(unsigned)idx[i] & (NTOT - 1u)] * g_inv_trace;
}

// ---------------------------------------------------------------------------
extern "C" void kernel_launch(void* const* d_in, const int* in_sizes, int n_in,
                              void* d_out, int out_size)
{
    const float* params = (const float*)d_in[0];      // (2, 4096, 1024)
    const float* Mr = (const float*)d_in[1];          // (4,2,2)
    const float* Mi = (const float*)d_in[2];          // (4,2,2)
    const int* idx = (const int*)d_in[3];             // (1e6,) int32
    float* out = (float*)d_out;

    const float* Ur = params;
    const float* Ui = params + (size_t)D * RK;

    pack_split<<<16384, 256>>>(Ur, Ui);

    const int smem_bytes = 2 * 8 * 128 * PITB;        // 163840
    cudaFuncSetAttribute(gemm_mma,
                         cudaFuncAttributeMaxDynamicSharedMemorySize, smem_bytes);
    gemm_mma<<<528, 256, smem_bytes>>>();

    trace_kernel<<<1, 256>>>();

    int dir = 0;
    for (int n = 1; n <= 6; n++) {
        qmt_sweep<<<4096, 256>>>(dir, Mr, Mi, 12 - 2 * n, n < 6 ? 1 : 0);
        dir ^= 1;
    }
    // final result (real plane) in gA_re

    int nq = in_sizes[3];
    gather_kernel<<<(nq + 255) / 256, 256>>>(idx, out, nq);
}